// round 10
// baseline (speedup 1.0000x reference)
#include <cuda_runtime.h>
#include <cstdint>

#define TT  512
#define BBT 64
#define ICC 512
#define HCC 512
#define LLN 2

#define SCAN_BLOCKS 128
#define DPB 4

typedef unsigned long long ull;

// ---------------- scratch ----------------------------------------------------
__device__ __align__(16) float g_A1[TT * BBT * 2 * HCC];   // [T][B][1024] (r | z)
__device__ __align__(16) float g_A2[TT * BBT * HCC];       // [T][B][512]
__device__ __align__(16) float g_l0[TT * BBT * HCC];       // layer-0 output stream
__device__ __align__(16) float g_h [BBT * HCC];
__device__ __align__(16) float g_rh[BBT * HCC];
__device__ ull g_flags[SCAN_BLOCKS];                       // per-block generation

// ---------------- f32x2 helpers ----------------------------------------------
__device__ __forceinline__ void ffma2(ull& d, ull a, ull b) {
    asm("fma.rn.f32x2 %0, %1, %2, %0;" : "+l"(d) : "l"(a), "l"(b));
}
__device__ __forceinline__ void upk2(ull v, float& a, float& b) {
    asm("mov.b64 {%0, %1}, %2;" : "=f"(a), "=f"(b) : "l"(v));
}
__device__ __forceinline__ ull pk2(float a, float b) {
    ull r; asm("mov.b64 %0, {%1, %2};" : "=l"(r) : "f"(a), "f"(b)); return r;
}
__device__ __forceinline__ ulonglong2 ldcg_u2(const ulonglong2* p) {
    ulonglong2 v;
    asm volatile("ld.global.cg.v2.u64 {%0, %1}, [%2];"
                 : "=l"(v.x), "=l"(v.y) : "l"(p));
    return v;
}

// ---------------- grid barrier (flag array, no atomics) -----------------------
__device__ __forceinline__ void grid_bar(ull target) {
    __syncthreads();
    if (threadIdx.x == 0) {
        asm volatile("st.release.gpu.global.b64 [%0], %1;"
                     :: "l"(&g_flags[blockIdx.x]), "l"(target) : "memory");
    }
    if (threadIdx.x < SCAN_BLOCKS) {
        ull v;
        do {
            asm volatile("ld.acquire.gpu.global.b64 %0, [%1];"
                         : "=l"(v) : "l"(&g_flags[threadIdx.x]) : "memory");
        } while (v < target);
    }
    __syncthreads();
}

// ---------------- multi-value butterfly reduce --------------------------------
// vals[32] per-thread; lane ln ends with the full cross-lane sum of vals[ln].
__device__ __forceinline__ float bfly32(float* vals, int ln) {
#pragma unroll
    for (int off = 1; off < 32; off <<= 1) {
        const int n = 32 / (2 * off);
#pragma unroll
        for (int i = 0; i < n; ++i) {
            bool up = (ln & off);
            float send = up ? vals[2 * i] : vals[2 * i + 1];
            float got  = __shfl_xor_sync(0xFFFFFFFFu, send, off);
            float keep = up ? vals[2 * i + 1] : vals[2 * i];
            vals[i] = keep + got;
        }
    }
    return vals[0];
}

// ---------------- precompute GEMM: A1/A2 = X @ Wx^T + b -----------------------
__global__ void __launch_bounds__(256) gru_pre(
    const float* __restrict__ Xext,
    const float* __restrict__ W1, const float* __restrict__ b1,
    const float* __restrict__ W2, const float* __restrict__ b2,
    int layer)
{
    const float* X   = (layer == 0) ? Xext : g_l0;
    const float* W1l = W1 + (size_t)layer * (2 * HCC) * (ICC + HCC);
    const float* W2l = W2 + (size_t)layer * HCC * (ICC + HCC);
    const float* b1l = b1 + layer * 2 * HCC;
    const float* b2l = b2 + layer * HCC;

    __shared__ float As[16][128];
    __shared__ float Bs[16][128];

    const int m0 = blockIdx.x * 128;
    const int n0 = blockIdx.y * 128;
    const int tid = threadIdx.x;
    const int isA1 = (n0 < 1024);
    const float* Wp = isA1 ? (W1l + (size_t)n0 * (ICC + HCC))
                           : (W2l + (size_t)(n0 - 1024) * (ICC + HCC));
    const int ty = tid >> 4;
    const int tx = tid & 15;

    ull acc[8][4];
#pragma unroll
    for (int i = 0; i < 8; ++i)
#pragma unroll
        for (int j = 0; j < 4; ++j) acc[i][j] = 0ull;

    for (int k0 = 0; k0 < ICC; k0 += 16) {
#pragma unroll
        for (int r = 0; r < 2; ++r) {
            int q = tid + r * 256;
            int row = q >> 2, kf = (q & 3) * 4;
            float4 v = *reinterpret_cast<const float4*>(&X[(size_t)(m0 + row) * ICC + k0 + kf]);
            As[kf + 0][row] = v.x; As[kf + 1][row] = v.y;
            As[kf + 2][row] = v.z; As[kf + 3][row] = v.w;
        }
#pragma unroll
        for (int r = 0; r < 2; ++r) {
            int q = tid + r * 256;
            int row = q >> 2, kf = (q & 3) * 4;
            float4 v = *reinterpret_cast<const float4*>(&Wp[(size_t)row * (ICC + HCC) + k0 + kf]);
            Bs[kf + 0][row] = v.x; Bs[kf + 1][row] = v.y;
            Bs[kf + 2][row] = v.z; Bs[kf + 3][row] = v.w;
        }
        __syncthreads();
#pragma unroll
        for (int k = 0; k < 16; ++k) {
            float4 a0 = *reinterpret_cast<const float4*>(&As[k][ty * 8]);
            float4 a1 = *reinterpret_cast<const float4*>(&As[k][ty * 8 + 4]);
            float4 b0 = *reinterpret_cast<const float4*>(&Bs[k][tx * 8]);
            float4 b1v = *reinterpret_cast<const float4*>(&Bs[k][tx * 8 + 4]);
            ull bp0 = pk2(b0.x, b0.y), bp1 = pk2(b0.z, b0.w);
            ull bp2 = pk2(b1v.x, b1v.y), bp3 = pk2(b1v.z, b1v.w);
            float av[8] = {a0.x, a0.y, a0.z, a0.w, a1.x, a1.y, a1.z, a1.w};
#pragma unroll
            for (int i = 0; i < 8; ++i) {
                ull ap = pk2(av[i], av[i]);
                ffma2(acc[i][0], ap, bp0);
                ffma2(acc[i][1], ap, bp1);
                ffma2(acc[i][2], ap, bp2);
                ffma2(acc[i][3], ap, bp3);
            }
        }
        __syncthreads();
    }

#pragma unroll
    for (int i = 0; i < 8; ++i) {
        int m = m0 + ty * 8 + i;
        int nb = n0 + tx * 8;
        float o[8];
#pragma unroll
        for (int j = 0; j < 4; ++j) upk2(acc[i][j], o[2 * j], o[2 * j + 1]);
        if (isA1) {
            float4 v0 = {o[0] + b1l[nb + 0], o[1] + b1l[nb + 1], o[2] + b1l[nb + 2], o[3] + b1l[nb + 3]};
            float4 v1 = {o[4] + b1l[nb + 4], o[5] + b1l[nb + 5], o[6] + b1l[nb + 6], o[7] + b1l[nb + 7]};
            *reinterpret_cast<float4*>(&g_A1[(size_t)m * 1024 + nb]) = v0;
            *reinterpret_cast<float4*>(&g_A1[(size_t)m * 1024 + nb + 4]) = v1;
        } else {
            int n2 = nb - 1024;
            float4 v0 = {o[0] + b2l[n2 + 0], o[1] + b2l[n2 + 1], o[2] + b2l[n2 + 2], o[3] + b2l[n2 + 3]};
            float4 v1 = {o[4] + b2l[n2 + 4], o[5] + b2l[n2 + 5], o[6] + b2l[n2 + 6], o[7] + b2l[n2 + 7]};
            *reinterpret_cast<float4*>(&g_A2[(size_t)m * 512 + n2]) = v0;
            *reinterpret_cast<float4*>(&g_A2[(size_t)m * 512 + n2 + 4]) = v1;
        }
    }
}

// ---------------- persistent scan kernel --------------------------------------
// 128 blocks x 256 threads (8 warps). Block owns hidden dims j0..j0+3.
// Warp w handles batches 8w..8w+7; lanes split K in float4 quads.
__global__ void __launch_bounds__(256, 1) gru_scan(
    const float* __restrict__ W1, const float* __restrict__ W2,
    const float* __restrict__ hiddens,
    float* __restrict__ dout, int layer)
{
    const int bid = blockIdx.x, tid = threadIdx.x;
    const int w = tid >> 5, ln = tid & 31;
    const int j0 = bid * DPB;
    const int oL = ln >> 3, bL = ln & 7;      // epilogue lane mapping (ln = oL*8+bL)
    const int BL = w * 8 + bL;

    __shared__ float4 sW1[8][128];   // [o][q]: o<4 -> r rows, o>=4 -> z rows; q = k/4
    __shared__ float4 sW2[4][128];
    __shared__ float  sZ[DPB][64];
    __shared__ float  sH[DPB][64];
    __shared__ ull    sBase;

    const float* W1l = W1 + (size_t)layer * (2 * HCC) * (ICC + HCC);
    const float* W2l = W2 + (size_t)layer * HCC * (ICC + HCC);
    float* outStream = (layer == 0) ? g_l0 : dout;
    float* hFinal = dout + (size_t)TT * BBT * HCC + (size_t)layer * BBT * HCC;

    if (tid == 0) sBase = *(volatile ull*)&g_flags[bid];

    // resident weights: per-output float4 over K (conflict-free LDS.128)
    for (int idx = tid; idx < 8 * 128; idx += 256) {
        int o = idx >> 7, q = idx & 127;
        int row = (o < 4) ? (j0 + o) : (512 + j0 + (o - 4));
        sW1[o][q] = *reinterpret_cast<const float4*>(&W1l[(size_t)row * 1024 + 512 + 4 * q]);
    }
    for (int idx = tid; idx < 4 * 128; idx += 256) {
        int o = idx >> 7, q = idx & 127;
        sW2[o][q] = *reinterpret_cast<const float4*>(&W2l[(size_t)(j0 + o) * 1024 + 512 + 4 * q]);
    }
    {
        int b = tid & 63, jd = tid >> 6;
        float v = hiddens[layer * HCC + j0 + jd];
        g_h[b * HCC + j0 + jd] = v;
        sH[jd][b] = v;
    }
    __syncthreads();

    ull bc = 0;
    grid_bar(sBase + (++bc));

    const ulonglong2* hU  = reinterpret_cast<const ulonglong2*>(g_h);
    const ulonglong2* rhU = reinterpret_cast<const ulonglong2*>(g_rh);

    for (int t = 0; t < TT; ++t) {
        const float* A1t = g_A1 + (size_t)t * BBT * 1024;
        const float* A2t = g_A2 + (size_t)t * BBT * 512;

        // prefetch precomputed input-side activations (no barrier dependency)
        float Ar = __ldg(&A1t[BL * 1024 + j0 + oL]);
        float Az = __ldg(&A1t[BL * 1024 + 512 + j0 + oL]);
        float Ag = __ldg(&A2t[BL * 512 + j0 + oL]);

        // ---- stage 1: pre = A1 + h @ W1h^T -> r (to g_rh), z (to sZ) ---------
        {
            ull acc[8][8];
#pragma unroll
            for (int o = 0; o < 8; ++o)
#pragma unroll
                for (int b = 0; b < 8; ++b) acc[o][b] = 0ull;

            ulonglong2 h2[2][8];
#pragma unroll
            for (int b = 0; b < 8; ++b)
                h2[0][b] = ldcg_u2(hU + (size_t)(w * 8 + b) * 128 + ln);
#pragma unroll
            for (int mq = 0; mq < 4; ++mq) {
                int q = ln + 32 * mq;
                if (mq < 3) {
#pragma unroll
                    for (int b = 0; b < 8; ++b)
                        h2[(mq + 1) & 1][b] = ldcg_u2(hU + (size_t)(w * 8 + b) * 128 + q + 32);
                }
                const ulonglong2* hc = h2[mq & 1];
#pragma unroll
                for (int o = 0; o < 8; ++o) {
                    ulonglong2 wv = *reinterpret_cast<const ulonglong2*>(&sW1[o][q]);
#pragma unroll
                    for (int b = 0; b < 8; ++b) {
                        ffma2(acc[o][b], wv.x, hc[b].x);
                        ffma2(acc[o][b], wv.y, hc[b].y);
                    }
                }
            }
            float vals[32];
#pragma unroll
            for (int o = 0; o < 4; ++o)
#pragma unroll
                for (int b = 0; b < 8; ++b) {
                    float x, y; upk2(acc[o][b], x, y);
                    vals[o * 8 + b] = x + y;
                }
            float redR = bfly32(vals, ln);
#pragma unroll
            for (int o = 4; o < 8; ++o)
#pragma unroll
                for (int b = 0; b < 8; ++b) {
                    float x, y; upk2(acc[o][b], x, y);
                    vals[(o - 4) * 8 + b] = x + y;
                }
            float redZ = bfly32(vals, ln);

            float preR = redR + Ar;
            float r = 1.0f / (1.0f + __expf(-preR));
            g_rh[BL * HCC + j0 + oL] = r * sH[oL][BL];
            float preZ = redZ + Az;
            sZ[oL][BL] = 1.0f / (1.0f + __expf(-preZ));
        }
        grid_bar(sBase + (++bc));

        // ---- stage 2: g = tanh(A2 + rh @ W2h^T); h = z*h + (1-z)*g -----------
        {
            ull acc2[4][8];
#pragma unroll
            for (int o = 0; o < 4; ++o)
#pragma unroll
                for (int b = 0; b < 8; ++b) acc2[o][b] = 0ull;

            ulonglong2 h2[2][8];
#pragma unroll
            for (int b = 0; b < 8; ++b)
                h2[0][b] = ldcg_u2(rhU + (size_t)(w * 8 + b) * 128 + ln);
#pragma unroll
            for (int mq = 0; mq < 4; ++mq) {
                int q = ln + 32 * mq;
                if (mq < 3) {
#pragma unroll
                    for (int b = 0; b < 8; ++b)
                        h2[(mq + 1) & 1][b] = ldcg_u2(rhU + (size_t)(w * 8 + b) * 128 + q + 32);
                }
                const ulonglong2* hc = h2[mq & 1];
#pragma unroll
                for (int o = 0; o < 4; ++o) {
                    ulonglong2 wv = *reinterpret_cast<const ulonglong2*>(&sW2[o][q]);
#pragma unroll
                    for (int b = 0; b < 8; ++b) {
                        ffma2(acc2[o][b], wv.x, hc[b].x);
                        ffma2(acc2[o][b], wv.y, hc[b].y);
                    }
                }
            }
            float vals[32];
#pragma unroll
            for (int o = 0; o < 4; ++o)
#pragma unroll
                for (int b = 0; b < 8; ++b) {
                    float x, y; upk2(acc2[o][b], x, y);
                    vals[o * 8 + b] = x + y;
                }
            float red = bfly32(vals, ln);

            float pre2 = red + Ag;
            float gg = tanhf(pre2);
            float z = sZ[oL][BL];
            float hold = sH[oL][BL];
            float hn = fmaf(z, hold - gg, gg);
            sH[oL][BL] = hn;
            g_h[BL * HCC + j0 + oL] = hn;
            outStream[((size_t)t * BBT + BL) * HCC + j0 + oL] = hn;
            if (t == TT - 1) hFinal[BL * HCC + j0 + oL] = hn;
        }
        grid_bar(sBase + (++bc));
    }
}

// ---------------- launch -------------------------------------------------------
extern "C" void kernel_launch(void* const* d_in, const int* in_sizes, int n_in,
                              void* d_out, int out_size)
{
    (void)in_sizes; (void)n_in; (void)out_size;
    const float* x       = (const float*)d_in[0];
    const float* hiddens = (const float*)d_in[1];
    const float* W1      = (const float*)d_in[2];
    const float* b1      = (const float*)d_in[3];
    const float* W2      = (const float*)d_in[4];
    const float* b2      = (const float*)d_in[5];
    float* out = (float*)d_out;

    dim3 pg(TT * BBT / 128, 1536 / 128);   // 256 x 12 blocks

    gru_pre <<<pg, 256>>>(x, W1, b1, W2, b2, 0);
    gru_scan<<<SCAN_BLOCKS, 256>>>(W1, W2, hiddens, out, 0);
    gru_pre <<<pg, 256>>>(x, W1, b1, W2, b2, 1);
    gru_scan<<<SCAN_BLOCKS, 256>>>(W1, W2, hiddens, out, 1);
}